// round 4
// baseline (speedup 1.0000x reference)
#include <cuda_runtime.h>
#include <cstdint>

// Table-batched embedding bag, SUM pooling.
// indices: int32 [T*B*L], offsets: int32 [T*B+1], weights: fp32 [T*E, 128],
// hash_size_cumsum: int32 [T+1], out: fp32 [B, T*128]
//
// One warp per bag; lane = one float4 of the 128-wide row (32*16B = 512B).
// Bag indices loaded with one coalesced lane-parallel LDG, distributed via
// shuffle. 8 row gathers issued back-to-back per batch (MLP_p1 = 8) before
// any accumulation, with 32-bit row arithmetic to keep register count low.

#define EMB_D 128

__global__ void __launch_bounds__(256) tbe_fwd_kernel(
    const int*   __restrict__ indices,
    const int*   __restrict__ offsets,
    const float* __restrict__ weights,
    const int*   __restrict__ hsc,
    float*       __restrict__ out,
    int batch, int n_tables, int num_bags)
{
    const int warp_global = (blockIdx.x * blockDim.x + threadIdx.x) >> 5;
    const int lane = threadIdx.x & 31;
    if (warp_global >= num_bags) return;

    const int seg   = warp_global;
    const int table = seg / batch;
    const int b     = seg - table * batch;

    const int base  = hsc[table];            // T*E <= 4M, fits int32
    const int start = offsets[seg];
    const int end   = offsets[seg + 1];

    const float4* __restrict__ wv = reinterpret_cast<const float4*>(weights);

    float4 a0 = make_float4(0.f, 0.f, 0.f, 0.f);
    float4 a1 = make_float4(0.f, 0.f, 0.f, 0.f);
    float4 a2 = make_float4(0.f, 0.f, 0.f, 0.f);
    float4 a3 = make_float4(0.f, 0.f, 0.f, 0.f);

    for (int chunk = start; chunk < end; chunk += 32) {
        const int cnt = min(32, end - chunk);
        // one coalesced index load for the whole chunk
        const int myidx = (lane < cnt) ? indices[chunk + lane] : 0;

        int k = 0;
        for (; k + 7 < cnt; k += 8) {
            // all shuffles first (independent), then 8 back-to-back LDG.128
            const unsigned r0 = (unsigned)(__shfl_sync(0xffffffffu, myidx, k)     + base);
            const unsigned r1 = (unsigned)(__shfl_sync(0xffffffffu, myidx, k + 1) + base);
            const unsigned r2 = (unsigned)(__shfl_sync(0xffffffffu, myidx, k + 2) + base);
            const unsigned r3 = (unsigned)(__shfl_sync(0xffffffffu, myidx, k + 3) + base);
            const unsigned r4 = (unsigned)(__shfl_sync(0xffffffffu, myidx, k + 4) + base);
            const unsigned r5 = (unsigned)(__shfl_sync(0xffffffffu, myidx, k + 5) + base);
            const unsigned r6 = (unsigned)(__shfl_sync(0xffffffffu, myidx, k + 6) + base);
            const unsigned r7 = (unsigned)(__shfl_sync(0xffffffffu, myidx, k + 7) + base);
            const float4 v0 = __ldg(wv + (size_t)r0 * 32u + lane);
            const float4 v1 = __ldg(wv + (size_t)r1 * 32u + lane);
            const float4 v2 = __ldg(wv + (size_t)r2 * 32u + lane);
            const float4 v3 = __ldg(wv + (size_t)r3 * 32u + lane);
            const float4 v4 = __ldg(wv + (size_t)r4 * 32u + lane);
            const float4 v5 = __ldg(wv + (size_t)r5 * 32u + lane);
            const float4 v6 = __ldg(wv + (size_t)r6 * 32u + lane);
            const float4 v7 = __ldg(wv + (size_t)r7 * 32u + lane);
            a0.x += v0.x + v4.x; a0.y += v0.y + v4.y; a0.z += v0.z + v4.z; a0.w += v0.w + v4.w;
            a1.x += v1.x + v5.x; a1.y += v1.y + v5.y; a1.z += v1.z + v5.z; a1.w += v1.w + v5.w;
            a2.x += v2.x + v6.x; a2.y += v2.y + v6.y; a2.z += v2.z + v6.z; a2.w += v2.w + v6.w;
            a3.x += v3.x + v7.x; a3.y += v3.y + v7.y; a3.z += v3.z + v7.z; a3.w += v3.w + v7.w;
        }
        for (; k + 3 < cnt; k += 4) {
            const unsigned r0 = (unsigned)(__shfl_sync(0xffffffffu, myidx, k)     + base);
            const unsigned r1 = (unsigned)(__shfl_sync(0xffffffffu, myidx, k + 1) + base);
            const unsigned r2 = (unsigned)(__shfl_sync(0xffffffffu, myidx, k + 2) + base);
            const unsigned r3 = (unsigned)(__shfl_sync(0xffffffffu, myidx, k + 3) + base);
            const float4 v0 = __ldg(wv + (size_t)r0 * 32u + lane);
            const float4 v1 = __ldg(wv + (size_t)r1 * 32u + lane);
            const float4 v2 = __ldg(wv + (size_t)r2 * 32u + lane);
            const float4 v3 = __ldg(wv + (size_t)r3 * 32u + lane);
            a0.x += v0.x; a0.y += v0.y; a0.z += v0.z; a0.w += v0.w;
            a1.x += v1.x; a1.y += v1.y; a1.z += v1.z; a1.w += v1.w;
            a2.x += v2.x; a2.y += v2.y; a2.z += v2.z; a2.w += v2.w;
            a3.x += v3.x; a3.y += v3.y; a3.z += v3.z; a3.w += v3.w;
        }
        for (; k < cnt; k++) {
            const unsigned r = (unsigned)(__shfl_sync(0xffffffffu, myidx, k) + base);
            const float4 v = __ldg(wv + (size_t)r * 32u + lane);
            a0.x += v.x; a0.y += v.y; a0.z += v.z; a0.w += v.w;
        }
    }

    float4 acc;
    acc.x = (a0.x + a1.x) + (a2.x + a3.x);
    acc.y = (a0.y + a1.y) + (a2.y + a3.y);
    acc.z = (a0.z + a1.z) + (a2.z + a3.z);
    acc.w = (a0.w + a1.w) + (a2.w + a3.w);

    float4* o = reinterpret_cast<float4*>(
        out + (size_t)b * ((size_t)n_tables * EMB_D) + (size_t)table * EMB_D);
    o[lane] = acc;
}

extern "C" void kernel_launch(void* const* d_in, const int* in_sizes, int n_in,
                              void* d_out, int out_size)
{
    const int*   indices = (const int*)d_in[0];
    const int*   offsets = (const int*)d_in[1];
    const float* weights = (const float*)d_in[2];
    const int*   hsc     = (const int*)d_in[3];
    float* out = (float*)d_out;

    const int num_bags = in_sizes[1] - 1;   // T*B
    const int n_tables = in_sizes[3] - 1;   // T
    const int batch    = num_bags / n_tables;

    const int warps_per_block = 8;          // 256 threads
    const int blocks = (num_bags + warps_per_block - 1) / warps_per_block;

    tbe_fwd_kernel<<<blocks, warps_per_block * 32>>>(
        indices, offsets, weights, hsc, out, batch, n_tables, num_bags);
}

// round 5
// speedup vs baseline: 1.0543x; 1.0543x over previous
#include <cuda_runtime.h>
#include <cstdint>

// Table-batched embedding bag, SUM pooling.
// indices: int32 [T*B*L], offsets: int32 [T*B+1], weights: fp32 [T*E, 128],
// hash_size_cumsum: int32 [T+1], out: fp32 [B, T*128]
//
// One warp per bag; lane = one float4 (16B) of the 512B row.
// Row gathers use cp.async.cg (LDGSTS) into a per-warp smem staging buffer:
// 8 rows in flight per warp with ZERO data registers, decoupling MLP from
// occupancy. Each thread writes and reads back only its own 16B smem slot,
// so no barriers are needed (wait_group 0 orders own writes).

#define EMB_D   128
#define SLOTS   8            // rows in flight per warp per wave
#define WARPS_PB 8           // 256 threads/block

__global__ void __launch_bounds__(256) tbe_fwd_kernel(
    const int*   __restrict__ indices,
    const int*   __restrict__ offsets,
    const float* __restrict__ weights,
    const int*   __restrict__ hsc,
    float*       __restrict__ out,
    int batch, int n_tables, int num_bags)
{
    // 8 warps * 8 slots * 32 lanes * 16B = 32 KB
    __shared__ float4 buf[WARPS_PB * SLOTS * 32];

    const int warp_global = (blockIdx.x * blockDim.x + threadIdx.x) >> 5;
    const int lane = threadIdx.x & 31;
    const int wib  = (threadIdx.x >> 5);
    if (warp_global >= num_bags) return;

    // this thread's private 16B staging slots: buf[wib*SLOTS*32 + s*32 + lane]
    float4* mybuf = buf + wib * (SLOTS * 32) + lane;
    const unsigned sbase =
        (unsigned)__cvta_generic_to_shared(mybuf);   // slot s at sbase + s*512

    const int seg   = warp_global;
    const int table = seg / batch;
    const int b     = seg - table * batch;

    const int base  = hsc[table];          // T*E <= 4M, fits int32
    const int start = offsets[seg];
    const int end   = offsets[seg + 1];

    const float4* __restrict__ wv = reinterpret_cast<const float4*>(weights);

    float4 a0 = make_float4(0.f, 0.f, 0.f, 0.f);
    float4 a1 = make_float4(0.f, 0.f, 0.f, 0.f);
    float4 a2 = make_float4(0.f, 0.f, 0.f, 0.f);
    float4 a3 = make_float4(0.f, 0.f, 0.f, 0.f);

    for (int chunk = start; chunk < end; chunk += 32) {
        const int cnt = min(32, end - chunk);
        // one coalesced index load for up to 32 bag entries
        const int myidx = (lane < cnt) ? indices[chunk + lane] : 0;

        for (int k = 0; k < cnt; k += SLOTS) {
            const int ns = min(SLOTS, cnt - k);

            // issue up to 8 row fetches, 16B per lane, no data registers
            #pragma unroll
            for (int s = 0; s < SLOTS; s++) {
                if (s < ns) {
                    const unsigned row =
                        (unsigned)(__shfl_sync(0xffffffffu, myidx, k + s) + base);
                    const float4* src = wv + (size_t)row * 32u + lane;
                    asm volatile(
                        "cp.async.cg.shared.global [%0], [%1], 16;\n"
                        :: "r"(sbase + s * 512u), "l"(src));
                }
            }
            asm volatile("cp.async.commit_group;\n");
            asm volatile("cp.async.wait_group 0;\n" ::: "memory");

            // accumulate from own smem slots (thread-local, no sync needed)
            #pragma unroll
            for (int s = 0; s < SLOTS; s += 4) {
                if (s < ns) {
                    const float4 v = mybuf[s * 32];
                    a0.x += v.x; a0.y += v.y; a0.z += v.z; a0.w += v.w;
                }
                if (s + 1 < ns) {
                    const float4 v = mybuf[(s + 1) * 32];
                    a1.x += v.x; a1.y += v.y; a1.z += v.z; a1.w += v.w;
                }
                if (s + 2 < ns) {
                    const float4 v = mybuf[(s + 2) * 32];
                    a2.x += v.x; a2.y += v.y; a2.z += v.z; a2.w += v.w;
                }
                if (s + 3 < ns) {
                    const float4 v = mybuf[(s + 3) * 32];
                    a3.x += v.x; a3.y += v.y; a3.z += v.z; a3.w += v.w;
                }
            }
        }
    }

    float4 acc;
    acc.x = (a0.x + a1.x) + (a2.x + a3.x);
    acc.y = (a0.y + a1.y) + (a2.y + a3.y);
    acc.z = (a0.z + a1.z) + (a2.z + a3.z);
    acc.w = (a0.w + a1.w) + (a2.w + a3.w);

    float4* o = reinterpret_cast<float4*>(
        out + (size_t)b * ((size_t)n_tables * EMB_D) + (size_t)table * EMB_D);
    o[lane] = acc;
}

extern "C" void kernel_launch(void* const* d_in, const int* in_sizes, int n_in,
                              void* d_out, int out_size)
{
    const int*   indices = (const int*)d_in[0];
    const int*   offsets = (const int*)d_in[1];
    const float* weights = (const float*)d_in[2];
    const int*   hsc     = (const int*)d_in[3];
    float* out = (float*)d_out;

    const int num_bags = in_sizes[1] - 1;   // T*B
    const int n_tables = in_sizes[3] - 1;   // T
    const int batch    = num_bags / n_tables;

    const int blocks = (num_bags + WARPS_PB - 1) / WARPS_PB;

    tbe_fwd_kernel<<<blocks, WARPS_PB * 32>>>(
        indices, offsets, weights, hsc, out, batch, n_tables, num_bags);
}